// round 15
// baseline (speedup 1.0000x reference)
#include <cuda_runtime.h>
#include <cuda_bf16.h>
#include <math.h>
#include <stdint.h>

// ---------------------------------------------------------------------------
// Problem constants
// ---------------------------------------------------------------------------
constexpr int BATCH = 16;
constexpr int HH    = 56;
constexpr int WWID  = 56;
constexpr int CDIM  = 384;
constexpr int NHEAD = 12;
constexpr int WSZ   = 7;
constexpr int SHIFT = 3;
constexpr int NTOK  = 49;
constexpr int NWIN  = BATCH * 64;
constexpr int TOK   = NWIN * NTOK;        // 50176
constexpr float ATT_SCALE = 0.17677669529663687f;
constexpr float LN_EPS    = 1e-3f;

// ---------------------------------------------------------------------------
// Scratch (device globals)
// ---------------------------------------------------------------------------
__device__ __nv_bfloat16 g_wins[TOK * CDIM];
__device__ __nv_bfloat16 g_qkv [TOK * 3 * CDIM];
__device__ __nv_bfloat16 g_att [TOK * CDIM];
__device__ float         g_x1  [TOK * CDIM];
__device__ __nv_bfloat16 g_ln2 [TOK * CDIM];
__device__ __nv_bfloat16 g_h   [TOK * 4 * CDIM];
// transposed bf16 weights [N, K]
__device__ __nv_bfloat16 g_wt_qkv [3 * CDIM * CDIM];
__device__ __nv_bfloat16 g_wt_proj[CDIM * CDIM];
__device__ __nv_bfloat16 g_wt_m1  [4 * CDIM * CDIM];
__device__ __nv_bfloat16 g_wt_m2  [4 * CDIM * CDIM];

// ---------------------------------------------------------------------------
// cp.async helpers
// ---------------------------------------------------------------------------
__device__ __forceinline__ void cp_async16(uint32_t smem, const void* g)
{
    asm volatile("cp.async.cg.shared.global [%0], [%1], 16;"
                 :: "r"(smem), "l"(g));
}
#define CP_COMMIT() asm volatile("cp.async.commit_group;")
#define CP_WAIT(n)  asm volatile("cp.async.wait_group %0;" :: "n"(n))

// ---------------------------------------------------------------------------
// Batched weight transpose + bf16 convert: 4 weights in ONE launch.
// ---------------------------------------------------------------------------
__global__ void __launch_bounds__(256)
transpose_all(const float* __restrict__ W0, __nv_bfloat16* __restrict__ T0,
              const float* __restrict__ W1, __nv_bfloat16* __restrict__ T1,
              const float* __restrict__ W2, __nv_bfloat16* __restrict__ T2,
              const float* __restrict__ W3, __nv_bfloat16* __restrict__ T3)
{
    const float* W; __nv_bfloat16* T; int K, N;
    switch (blockIdx.z) {
        case 0: W = W0; T = T0; K = 384;  N = 1152; break;
        case 1: W = W1; T = T1; K = 384;  N = 384;  break;
        case 2: W = W2; T = T2; K = 384;  N = 1536; break;
        default:W = W3; T = T3; K = 1536; N = 384;  break;
    }
    int kb = blockIdx.x * 32, nb = blockIdx.y * 32;
    if (kb >= K || nb >= N) return;

    __shared__ float t[32][33];
    int x = threadIdx.x & 31, y = threadIdx.x >> 5;   // 32 x 8
    #pragma unroll
    for (int dy = 0; dy < 32; dy += 8)
        t[y + dy][x] = W[(size_t)(kb + y + dy) * N + nb + x];
    __syncthreads();
    #pragma unroll
    for (int dy = 0; dy < 32; dy += 8)
        T[(size_t)(nb + y + dy) * K + kb + x] = __float2bfloat16(t[x][y + dy]);
}

// ---------------------------------------------------------------------------
// LayerNorm: one WARP per token, 8 tokens per 256-thread block.
// gather=1 fuses roll(-3,+3) + window partition. bf16 output.
// ---------------------------------------------------------------------------
__global__ void __launch_bounds__(256)
ln_kernel(const float* __restrict__ X, const float* __restrict__ gam,
          const float* __restrict__ bet, __nv_bfloat16* __restrict__ Y, int gather)
{
    const int warp = threadIdx.x >> 5, lane = threadIdx.x & 31;
    const int tok = blockIdx.x * 8 + warp;
    int src = tok;
    if (gather) {
        int win = tok / NTOK, n = tok % NTOK;
        int b  = win >> 6, wi = win & 63;
        int wh = wi >> 3,  ww = wi & 7;
        int i  = n / WSZ,  j  = n % WSZ;
        int hs = wh * WSZ + i, ws = ww * WSZ + j;
        int sh = hs + SHIFT; if (sh >= HH)  sh -= HH;
        int sw = ws - SHIFT; if (sw < 0)    sw += WWID;
        src = (b * HH + sh) * WWID + sw;
    }
    const float4* xp = (const float4*)(X + (size_t)src * CDIM);
    float4 v0 = xp[lane], v1 = xp[lane + 32], v2 = xp[lane + 64];

    float s  = v0.x + v0.y + v0.z + v0.w
             + v1.x + v1.y + v1.z + v1.w
             + v2.x + v2.y + v2.z + v2.w;
    float s2 = v0.x * v0.x + v0.y * v0.y + v0.z * v0.z + v0.w * v0.w
             + v1.x * v1.x + v1.y * v1.y + v1.z * v1.z + v1.w * v1.w
             + v2.x * v2.x + v2.y * v2.y + v2.z * v2.z + v2.w * v2.w;
    #pragma unroll
    for (int off = 16; off; off >>= 1) {
        s  += __shfl_xor_sync(~0u, s,  off);
        s2 += __shfl_xor_sync(~0u, s2, off);
    }
    const float mu = s * (1.0f / CDIM);
    const float rs = rsqrtf(s2 * (1.0f / CDIM) - mu * mu + LN_EPS);

    const float4* gp = (const float4*)gam;
    const float4* bp = (const float4*)bet;
    uint2* yp = (uint2*)(Y + (size_t)tok * CDIM);

    #pragma unroll
    for (int q = 0; q < 3; q++) {
        float4 v = (q == 0) ? v0 : (q == 1) ? v1 : v2;
        float4 gg = gp[lane + q * 32];
        float4 bb = bp[lane + q * 32];
        float o0 = (v.x - mu) * rs * gg.x + bb.x;
        float o1 = (v.y - mu) * rs * gg.y + bb.y;
        float o2 = (v.z - mu) * rs * gg.z + bb.z;
        float o3 = (v.w - mu) * rs * gg.w + bb.w;
        __nv_bfloat162 p0 = __floats2bfloat162_rn(o0, o1);
        __nv_bfloat162 p1 = __floats2bfloat162_rn(o2, o3);
        yp[lane + q * 32] = make_uint2(*(unsigned*)&p0, *(unsigned*)&p1);
    }
}

__device__ __forceinline__ int dest_row(int tok)
{
    int win = tok / NTOK, n = tok % NTOK;
    int b  = win >> 6, wi = win & 63;
    int wh = wi >> 3,  ww = wi & 7;
    int i  = n / WSZ,  j  = n % WSZ;
    int hs = wh * WSZ + i, ws = ww * WSZ + j;
    int h = hs + SHIFT; if (h >= HH)   h -= HH;
    int w = ws + SHIFT; if (w >= WWID) w -= WWID;
    return (b * HH + h) * WWID + w;
}

// ---------------------------------------------------------------------------
// bf16 mma.sync GEMM. 128x128 CTA tile, 8 warps (64x32), 4-stage cp.async
// pipeline, BK=32/stage — proven backbone, unchanged.
// ---------------------------------------------------------------------------
__device__ __forceinline__ void mma_bf16(float* c, const unsigned* a, const unsigned* b)
{
    asm volatile(
        "mma.sync.aligned.m16n8k16.row.col.f32.bf16.bf16.f32 "
        "{%0,%1,%2,%3}, {%4,%5,%6,%7}, {%8,%9}, {%0,%1,%2,%3};"
        : "+f"(c[0]), "+f"(c[1]), "+f"(c[2]), "+f"(c[3])
        : "r"(a[0]), "r"(a[1]), "r"(a[2]), "r"(a[3]), "r"(b[0]), "r"(b[1]));
}

template<int MODE>
__global__ void __launch_bounds__(256)
gemm_tc(const __nv_bfloat16* __restrict__ A, const __nv_bfloat16* __restrict__ Bt,
        const float* __restrict__ bias, const float* __restrict__ res,
        float* __restrict__ Cf, __nv_bfloat16* __restrict__ Cb,
        int M, int N, int K)
{
    constexpr int STAGES = 4;
    __shared__ __align__(16) unsigned As[STAGES][2048];
    __shared__ __align__(16) unsigned Bs[STAGES][2048];

    const int tid  = threadIdx.x;
    const int bm   = blockIdx.y * 128, bn = blockIdx.x * 128;
    const int warp = tid >> 5, lane = tid & 31;
    const int wm   = warp & 1, wn = warp >> 1;       // 2 x 4 warp grid

    const int ma = tid >> 1, ha = tid & 1;
    const __nv_bfloat16* Ag = A + (size_t)(bm + ma) * K + ha * 8;
    const int aOff = ((ma >> 4) * 4 + ((ma >> 3) & 1) + 2 * ha) * 32
                   + (((ma & 7) * 4) ^ (ha << 4));

    const int nb = tid >> 1, hb = tid & 1;
    const __nv_bfloat16* Bg = Bt + (size_t)(bn + nb) * K + hb * 8;
    const int bOff = nb * 8 + ((hb * 4) ^ (((nb >> 2) & 1) << 2));

    const uint32_t aSm = (uint32_t)__cvta_generic_to_shared(&As[0][0]) + aOff * 4;
    const uint32_t bSm = (uint32_t)__cvta_generic_to_shared(&Bs[0][0]) + bOff * 4;

    float acc[16][4];
    #pragma unroll
    for (int i = 0; i < 16; i++)
        #pragma unroll
        for (int j = 0; j < 4; j++) acc[i][j] = 0.f;

    const int NC = K >> 5;

    #pragma unroll
    for (int s = 0; s < STAGES - 1; s++) {
        cp_async16(aSm + s * 8192,        Ag + s * 32);
        cp_async16(aSm + s * 8192 + 4096, Ag + s * 32 + 16);
        cp_async16(bSm + s * 8192,        Bg + s * 32);
        cp_async16(bSm + s * 8192 + 4096, Bg + s * 32 + 16);
        CP_COMMIT();
    }

    for (int c = 0; c < NC; c++) {
        const int st = c & (STAGES - 1);
        CP_WAIT(STAGES - 2);
        __syncthreads();

        #pragma unroll
        for (int sub = 0; sub < 2; sub++) {
            const unsigned* Asb = &As[st][sub * 1024];
            const unsigned* Bsb = &Bs[st][sub * 1024];
            unsigned afr[4][4], bfr[4][2];
            #pragma unroll
            for (int i = 0; i < 4; i++) {
                int blk = (wm * 4 + i) * 4;
                afr[i][0] = Asb[(blk + 0) * 32 + lane];
                afr[i][1] = Asb[(blk + 1) * 32 + lane];
                afr[i][2] = Asb[(blk + 2) * 32 + (lane ^ 16)];
                afr[i][3] = Asb[(blk + 3) * 32 + (lane ^ 16)];
            }
            #pragma unroll
            for (int j = 0; j < 4; j++) {
                int n    = wn * 32 + j * 8 + (lane >> 2);
                int flip = ((n >> 2) & 1) << 2;
                bfr[j][0] = Bsb[n * 8 + ((lane & 3) ^ flip)];
                bfr[j][1] = Bsb[n * 8 + (((lane & 3) + 4) ^ flip)];
            }
            #pragma unroll
            for (int i = 0; i < 4; i++)
                #pragma unroll
                for (int j = 0; j < 4; j++)
                    mma_bf16(acc[i * 4 + j], afr[i], bfr[j]);
        }

        const int nc = c + STAGES - 1;
        if (nc < NC) {
            const int ns = nc & (STAGES - 1);
            cp_async16(aSm + ns * 8192,        Ag + (size_t)nc * 32);
            cp_async16(aSm + ns * 8192 + 4096, Ag + (size_t)nc * 32 + 16);
            cp_async16(bSm + ns * 8192,        Bg + (size_t)nc * 32);
            cp_async16(bSm + ns * 8192 + 4096, Bg + (size_t)nc * 32 + 16);
        }
        CP_COMMIT();
    }

    // ---- epilogue ----
    const int g = lane >> 2, t = lane & 3;
    #pragma unroll
    for (int i = 0; i < 4; i++) {
        int r0 = bm + wm * 64 + i * 16 + g;
        int r1 = r0 + 8;
        int d0 = (MODE == 2) ? dest_row(r0) : r0;
        int d1 = (MODE == 2) ? dest_row(r1) : r1;
        #pragma unroll
        for (int j = 0; j < 4; j++) {
            int col = bn + wn * 32 + j * 8 + t * 2;
            float bc0 = bias[col], bc1 = bias[col + 1];
            float v00 = acc[i * 4 + j][0] + bc0;
            float v01 = acc[i * 4 + j][1] + bc1;
            float v10 = acc[i * 4 + j][2] + bc0;
            float v11 = acc[i * 4 + j][3] + bc1;
            if (MODE == 0 || MODE == 1) {
                if (MODE == 1) {
                    v00 = 0.5f * v00 * (1.0f + erff(v00 * 0.70710678118654752f));
                    v01 = 0.5f * v01 * (1.0f + erff(v01 * 0.70710678118654752f));
                    v10 = 0.5f * v10 * (1.0f + erff(v10 * 0.70710678118654752f));
                    v11 = 0.5f * v11 * (1.0f + erff(v11 * 0.70710678118654752f));
                }
                __nv_bfloat162 p0 = __floats2bfloat162_rn(v00, v01);
                __nv_bfloat162 p1 = __floats2bfloat162_rn(v10, v11);
                *(unsigned*)&Cb[(size_t)r0 * N + col] = *(unsigned*)&p0;
                *(unsigned*)&Cb[(size_t)r1 * N + col] = *(unsigned*)&p1;
            } else {
                v00 += res[(size_t)d0 * N + col];
                v01 += res[(size_t)d0 * N + col + 1];
                v10 += res[(size_t)d1 * N + col];
                v11 += res[(size_t)d1 * N + col + 1];
                *(float2*)&Cf[(size_t)d0 * N + col] = make_float2(v00, v01);
                *(float2*)&Cf[(size_t)d1 * N + col] = make_float2(v10, v11);
            }
        }
    }
}

// ---------------------------------------------------------------------------
// Attention: one CTA per (window, head); bf16 qkv in, bf16 out.
// - rel-pos head column preloaded to SMEM (169 LDG vs 2401 scattered)
// - K loaded straight from global into registers (no kk SMEM array)
// - QK: 4 groups x 64 threads, K pinned in regs, q reads warp-broadcast
// Dot-product order identical to round-14 -> bitwise-same S.
// ---------------------------------------------------------------------------
__device__ __forceinline__ void unpack8(uint4 h, float* dst, float scale)
{
    const __nv_bfloat162* p = (const __nv_bfloat162*)&h;
    #pragma unroll
    for (int e = 0; e < 4; e++) {
        dst[e * 2]     = __low2float(p[e])  * scale;
        dst[e * 2 + 1] = __high2float(p[e]) * scale;
    }
}

__global__ void __launch_bounds__(256)
attn_kernel(const __nv_bfloat16* __restrict__ qkv, const float* __restrict__ relt,
            __nv_bfloat16* __restrict__ outp)
{
    int blk  = blockIdx.x;
    int win  = blk / NHEAD;
    int head = blk % NHEAD;

    __shared__ float q [49][36];
    __shared__ float vv[49][36];
    __shared__ float S [49][56];
    __shared__ float rel_s[169];
    __shared__ int   cnt[49];

    int tid = threadIdx.x;

    // ---- K straight to registers (independent of SMEM; overlaps fills) ----
    const int grp = tid >> 6;          // 4 groups
    const int m   = tid & 63;
    const bool mv = (m < 49);
    float kr[32];
    if (mv) {
        const uint4* kg = (const uint4*)(qkv + (size_t)(win * 49 + m) * 1152
                                         + head * 32 + 384);
        uint4 t0 = kg[0], t1 = kg[1], t2 = kg[2], t3 = kg[3];
        unpack8(t0, kr,      1.0f);
        unpack8(t1, kr + 8,  1.0f);
        unpack8(t2, kr + 16, 1.0f);
        unpack8(t3, kr + 24, 1.0f);
    }

    // ---- q / v to SMEM; rel-pos column; region ids ----
    if (tid < 49 * 4) {
        int n = tid >> 2, dc = tid & 3;
        size_t base = (size_t)(win * 49 + n) * 1152 + head * 32 + dc * 8;
        uint4 hq = *(const uint4*)&qkv[base];
        uint4 hv = *(const uint4*)&qkv[base + 768];
        unpack8(hq, &q [n][dc * 8], ATT_SCALE);
        unpack8(hv, &vv[n][dc * 8], 1.0f);
    }
    if (tid < 169) rel_s[tid] = relt[tid * NHEAD + head];
    if (tid < 49) {
        int wi = win & 63;
        int wh = wi >> 3, ww = wi & 7;
        int i = tid / 7, j = tid % 7;
        int h = wh * 7 + i, w = ww * 7 + j;
        int rh = (h < HH - WSZ)   ? 0 : (h < HH - SHIFT   ? 1 : 2);
        int rw = (w < WWID - WSZ) ? 0 : (w < WWID - SHIFT ? 1 : 2);
        cnt[tid] = rh * 3 + rw;
    }
    __syncthreads();

    // ---- QK^T + bias + mask ----
    {
        int cm = 0, mdiv = 0, mmod = 0;
        if (mv) { cm = cnt[m]; mdiv = m / 7; mmod = m % 7; }
        const float4* krq = (const float4*)kr;

        for (int n = grp; n < 49; n += 4) {
            const float4* qr = (const float4*)q[n];
            float acc = 0.f;
            #pragma unroll
            for (int c = 0; c < 8; c++) {
                float4 a = qr[c];          // warp-broadcast LDS.128
                float4 k4 = krq[c];
                acc = fmaf(a.x, k4.x, acc);
                acc = fmaf(a.y, k4.y, acc);
                acc = fmaf(a.z, k4.z, acc);
                acc = fmaf(a.w, k4.w, acc);
            }
            if (mv) {
                int di = n / 7 - mdiv + 6;
                int dj = n % 7 - mmod + 6;
                float bias = rel_s[di * 13 + dj];
                float mask = (cnt[n] != cm) ? -100.f : 0.f;
                S[n][m] = acc + bias + mask;
            }
        }
    }
    __syncthreads();

    // ---- softmax (warp per row) ----
    int wid = tid >> 5, lane = tid & 31;
    for (int n = wid; n < 49; n += 8) {
        float v0 = S[n][lane];
        float v1 = (lane < 17) ? S[n][lane + 32] : -1e30f;
        float mx = fmaxf(v0, v1);
        #pragma unroll
        for (int off = 16; off; off >>= 1)
            mx = fmaxf(mx, __shfl_xor_sync(~0u, mx, off));
        float e0 = expf(v0 - mx);
        float e1 = (lane < 17) ? expf(v1 - mx) : 0.f;
        float sm = e0 + e1;
        #pragma unroll
        for (int off = 16; off; off >>= 1)
            sm += __shfl_xor_sync(~0u, sm, off);
        float inv = 1.f / sm;
        S[n][lane] = e0 * inv;
        if (lane < 17) S[n][lane + 32] = e1 * inv;
    }
    __syncthreads();

    // ---- P @ V, bf16 out ----
    for (int idx = tid; idx < 49 * 8; idx += 256) {
        int n = idx >> 3, dq = idx & 7;
        float a0 = 0.f, a1 = 0.f, a2 = 0.f, a3 = 0.f;
        #pragma unroll 7
        for (int mm = 0; mm < 49; mm++) {
            float s = S[n][mm];
            float4 v = *(const float4*)&vv[mm][dq * 4];
            a0 = fmaf(s, v.x, a0);
            a1 = fmaf(s, v.y, a1);
            a2 = fmaf(s, v.z, a2);
            a3 = fmaf(s, v.w, a3);
        }
        __nv_bfloat162 p0 = __floats2bfloat162_rn(a0, a1);
        __nv_bfloat162 p1 = __floats2bfloat162_rn(a2, a3);
        size_t o = (size_t)(win * 49 + n) * 384 + head * 32 + dq * 4;
        *(uint2*)&outp[o] = make_uint2(*(unsigned*)&p0, *(unsigned*)&p1);
    }
}

// ---------------------------------------------------------------------------
// Launch
// ---------------------------------------------------------------------------
extern "C" void kernel_launch(void* const* d_in, const int* in_sizes, int n_in,
                              void* d_out, int out_size)
{
    const float* x      = (const float*)d_in[0];
    const float* ln1_g  = (const float*)d_in[1];
    const float* ln1_b  = (const float*)d_in[2];
    const float* ln2_g  = (const float*)d_in[3];
    const float* ln2_b  = (const float*)d_in[4];
    const float* qkv_w  = (const float*)d_in[5];
    const float* qkv_b  = (const float*)d_in[6];
    const float* proj_w = (const float*)d_in[7];
    const float* proj_b = (const float*)d_in[8];
    const float* mlp_w1 = (const float*)d_in[9];
    const float* mlp_b1 = (const float*)d_in[10];
    const float* mlp_w2 = (const float*)d_in[11];
    const float* mlp_b2 = (const float*)d_in[12];
    const float* relt   = (const float*)d_in[13];
    float* out = (float*)d_out;

    __nv_bfloat16 *wins, *qkvb, *att, *ln2o, *hbuf, *wtq, *wtp, *wt1, *wt2;
    float *x1;
    cudaGetSymbolAddress((void**)&wins, g_wins);
    cudaGetSymbolAddress((void**)&qkvb, g_qkv);
    cudaGetSymbolAddress((void**)&att,  g_att);
    cudaGetSymbolAddress((void**)&x1,   g_x1);
    cudaGetSymbolAddress((void**)&ln2o, g_ln2);
    cudaGetSymbolAddress((void**)&hbuf, g_h);
    cudaGetSymbolAddress((void**)&wtq,  g_wt_qkv);
    cudaGetSymbolAddress((void**)&wtp,  g_wt_proj);
    cudaGetSymbolAddress((void**)&wt1,  g_wt_m1);
    cudaGetSymbolAddress((void**)&wt2,  g_wt_m2);

    // 0. all weight transposes in one launch
    transpose_all<<<dim3(48, 48, 4), 256>>>(qkv_w, wtq, proj_w, wtp,
                                            mlp_w1, wt1, mlp_w2, wt2);

    // 1. LN1 + cyclic shift + window partition -> bf16
    ln_kernel<<<TOK / 8, 256>>>(x, ln1_g, ln1_b, wins, 1);

    // 2. QKV GEMM: [50176,384] @ [384,1152] -> bf16
    gemm_tc<0><<<dim3(9, TOK / 128), 256>>>(
        wins, wtq, qkv_b, nullptr, nullptr, qkvb, TOK, 1152, 384);

    // 3. Windowed attention -> bf16
    attn_kernel<<<NWIN * NHEAD, 256>>>(qkvb, relt, att);

    // 4. Proj GEMM + window reverse + reverse roll + residual -> fp32
    gemm_tc<2><<<dim3(3, TOK / 128), 256>>>(
        att, wtp, proj_b, x, x1, nullptr, TOK, 384, 384);

    // 5. LN2 -> bf16
    ln_kernel<<<TOK / 8, 256>>>(x1, ln2_g, ln2_b, ln2o, 0);

    // 6. MLP1 + GELU: [50176,384] @ [384,1536] -> bf16
    gemm_tc<1><<<dim3(12, TOK / 128), 256>>>(
        ln2o, wt1, mlp_b1, nullptr, nullptr, hbuf, TOK, 1536, 384);

    // 7. MLP2 + residual: [50176,1536] @ [1536,384] -> d_out
    gemm_tc<3><<<dim3(3, TOK / 128), 256>>>(
        hbuf, wt2, mlp_b2, x1, out, nullptr, TOK, 384, 1536);
}

// round 16
// speedup vs baseline: 1.0792x; 1.0792x over previous
#include <cuda_runtime.h>
#include <cuda_bf16.h>
#include <math.h>
#include <stdint.h>

// ---------------------------------------------------------------------------
// Problem constants
// ---------------------------------------------------------------------------
constexpr int BATCH = 16;
constexpr int HH    = 56;
constexpr int WWID  = 56;
constexpr int CDIM  = 384;
constexpr int NHEAD = 12;
constexpr int WSZ   = 7;
constexpr int SHIFT = 3;
constexpr int NTOK  = 49;
constexpr int NWIN  = BATCH * 64;
constexpr int TOK   = NWIN * NTOK;        // 50176
constexpr float ATT_SCALE = 0.17677669529663687f;
constexpr float LN_EPS    = 1e-3f;

// ---------------------------------------------------------------------------
// Scratch (device globals)
// ---------------------------------------------------------------------------
__device__ __nv_bfloat16 g_wins[TOK * CDIM];
__device__ __nv_bfloat16 g_qkv [TOK * 3 * CDIM];
__device__ __nv_bfloat16 g_att [TOK * CDIM];
__device__ float         g_x1  [TOK * CDIM];
__device__ __nv_bfloat16 g_ln2 [TOK * CDIM];
__device__ __nv_bfloat16 g_h   [TOK * 4 * CDIM];
// transposed bf16 weights [N, K]
__device__ __nv_bfloat16 g_wt_qkv [3 * CDIM * CDIM];
__device__ __nv_bfloat16 g_wt_proj[CDIM * CDIM];
__device__ __nv_bfloat16 g_wt_m1  [4 * CDIM * CDIM];
__device__ __nv_bfloat16 g_wt_m2  [4 * CDIM * CDIM];

// ---------------------------------------------------------------------------
// cp.async helpers
// ---------------------------------------------------------------------------
__device__ __forceinline__ void cp_async16(uint32_t smem, const void* g)
{
    asm volatile("cp.async.cg.shared.global [%0], [%1], 16;"
                 :: "r"(smem), "l"(g));
}
#define CP_COMMIT() asm volatile("cp.async.commit_group;")
#define CP_WAIT(n)  asm volatile("cp.async.wait_group %0;" :: "n"(n))

// ---------------------------------------------------------------------------
// Batched weight transpose + bf16 convert: 4 weights in ONE launch.
// ---------------------------------------------------------------------------
__global__ void __launch_bounds__(256)
transpose_all(const float* __restrict__ W0, __nv_bfloat16* __restrict__ T0,
              const float* __restrict__ W1, __nv_bfloat16* __restrict__ T1,
              const float* __restrict__ W2, __nv_bfloat16* __restrict__ T2,
              const float* __restrict__ W3, __nv_bfloat16* __restrict__ T3)
{
    const float* W; __nv_bfloat16* T; int K, N;
    switch (blockIdx.z) {
        case 0: W = W0; T = T0; K = 384;  N = 1152; break;
        case 1: W = W1; T = T1; K = 384;  N = 384;  break;
        case 2: W = W2; T = T2; K = 384;  N = 1536; break;
        default:W = W3; T = T3; K = 1536; N = 384;  break;
    }
    int kb = blockIdx.x * 32, nb = blockIdx.y * 32;
    if (kb >= K || nb >= N) return;

    __shared__ float t[32][33];
    int x = threadIdx.x & 31, y = threadIdx.x >> 5;   // 32 x 8
    #pragma unroll
    for (int dy = 0; dy < 32; dy += 8)
        t[y + dy][x] = W[(size_t)(kb + y + dy) * N + nb + x];
    __syncthreads();
    #pragma unroll
    for (int dy = 0; dy < 32; dy += 8)
        T[(size_t)(nb + y + dy) * K + kb + x] = __float2bfloat16(t[x][y + dy]);
}

// ---------------------------------------------------------------------------
// LayerNorm: one WARP per token, 8 tokens per 256-thread block.
// gather=1 fuses roll(-3,+3) + window partition. bf16 output.
// ---------------------------------------------------------------------------
__global__ void __launch_bounds__(256)
ln_kernel(const float* __restrict__ X, const float* __restrict__ gam,
          const float* __restrict__ bet, __nv_bfloat16* __restrict__ Y, int gather)
{
    const int warp = threadIdx.x >> 5, lane = threadIdx.x & 31;
    const int tok = blockIdx.x * 8 + warp;
    int src = tok;
    if (gather) {
        int win = tok / NTOK, n = tok % NTOK;
        int b  = win >> 6, wi = win & 63;
        int wh = wi >> 3,  ww = wi & 7;
        int i  = n / WSZ,  j  = n % WSZ;
        int hs = wh * WSZ + i, ws = ww * WSZ + j;
        int sh = hs + SHIFT; if (sh >= HH)  sh -= HH;
        int sw = ws - SHIFT; if (sw < 0)    sw += WWID;
        src = (b * HH + sh) * WWID + sw;
    }
    const float4* xp = (const float4*)(X + (size_t)src * CDIM);
    float4 v0 = xp[lane], v1 = xp[lane + 32], v2 = xp[lane + 64];

    float s  = v0.x + v0.y + v0.z + v0.w
             + v1.x + v1.y + v1.z + v1.w
             + v2.x + v2.y + v2.z + v2.w;
    float s2 = v0.x * v0.x + v0.y * v0.y + v0.z * v0.z + v0.w * v0.w
             + v1.x * v1.x + v1.y * v1.y + v1.z * v1.z + v1.w * v1.w
             + v2.x * v2.x + v2.y * v2.y + v2.z * v2.z + v2.w * v2.w;
    #pragma unroll
    for (int off = 16; off; off >>= 1) {
        s  += __shfl_xor_sync(~0u, s,  off);
        s2 += __shfl_xor_sync(~0u, s2, off);
    }
    const float mu = s * (1.0f / CDIM);
    const float rs = rsqrtf(s2 * (1.0f / CDIM) - mu * mu + LN_EPS);

    const float4* gp = (const float4*)gam;
    const float4* bp = (const float4*)bet;
    uint2* yp = (uint2*)(Y + (size_t)tok * CDIM);

    #pragma unroll
    for (int q = 0; q < 3; q++) {
        float4 v = (q == 0) ? v0 : (q == 1) ? v1 : v2;
        float4 gg = gp[lane + q * 32];
        float4 bb = bp[lane + q * 32];
        float o0 = (v.x - mu) * rs * gg.x + bb.x;
        float o1 = (v.y - mu) * rs * gg.y + bb.y;
        float o2 = (v.z - mu) * rs * gg.z + bb.z;
        float o3 = (v.w - mu) * rs * gg.w + bb.w;
        __nv_bfloat162 p0 = __floats2bfloat162_rn(o0, o1);
        __nv_bfloat162 p1 = __floats2bfloat162_rn(o2, o3);
        yp[lane + q * 32] = make_uint2(*(unsigned*)&p0, *(unsigned*)&p1);
    }
}

__device__ __forceinline__ int dest_row(int tok)
{
    int win = tok / NTOK, n = tok % NTOK;
    int b  = win >> 6, wi = win & 63;
    int wh = wi >> 3,  ww = wi & 7;
    int i  = n / WSZ,  j  = n % WSZ;
    int hs = wh * WSZ + i, ws = ww * WSZ + j;
    int h = hs + SHIFT; if (h >= HH)   h -= HH;
    int w = ws + SHIFT; if (w >= WWID) w -= WWID;
    return (b * HH + h) * WWID + w;
}

// ---------------------------------------------------------------------------
// bf16 mma.sync GEMM. 128x128 CTA tile, 8 warps (64x32), 4-stage cp.async
// pipeline, BK=32/stage — proven backbone, unchanged.
// ---------------------------------------------------------------------------
__device__ __forceinline__ void mma_bf16(float* c, const unsigned* a, const unsigned* b)
{
    asm volatile(
        "mma.sync.aligned.m16n8k16.row.col.f32.bf16.bf16.f32 "
        "{%0,%1,%2,%3}, {%4,%5,%6,%7}, {%8,%9}, {%0,%1,%2,%3};"
        : "+f"(c[0]), "+f"(c[1]), "+f"(c[2]), "+f"(c[3])
        : "r"(a[0]), "r"(a[1]), "r"(a[2]), "r"(a[3]), "r"(b[0]), "r"(b[1]));
}

template<int MODE>
__global__ void __launch_bounds__(256)
gemm_tc(const __nv_bfloat16* __restrict__ A, const __nv_bfloat16* __restrict__ Bt,
        const float* __restrict__ bias, const float* __restrict__ res,
        float* __restrict__ Cf, __nv_bfloat16* __restrict__ Cb,
        int M, int N, int K)
{
    constexpr int STAGES = 4;
    __shared__ __align__(16) unsigned As[STAGES][2048];
    __shared__ __align__(16) unsigned Bs[STAGES][2048];

    const int tid  = threadIdx.x;
    const int bm   = blockIdx.y * 128, bn = blockIdx.x * 128;
    const int warp = tid >> 5, lane = tid & 31;
    const int wm   = warp & 1, wn = warp >> 1;       // 2 x 4 warp grid

    const int ma = tid >> 1, ha = tid & 1;
    const __nv_bfloat16* Ag = A + (size_t)(bm + ma) * K + ha * 8;
    const int aOff = ((ma >> 4) * 4 + ((ma >> 3) & 1) + 2 * ha) * 32
                   + (((ma & 7) * 4) ^ (ha << 4));

    const int nb = tid >> 1, hb = tid & 1;
    const __nv_bfloat16* Bg = Bt + (size_t)(bn + nb) * K + hb * 8;
    const int bOff = nb * 8 + ((hb * 4) ^ (((nb >> 2) & 1) << 2));

    const uint32_t aSm = (uint32_t)__cvta_generic_to_shared(&As[0][0]) + aOff * 4;
    const uint32_t bSm = (uint32_t)__cvta_generic_to_shared(&Bs[0][0]) + bOff * 4;

    float acc[16][4];
    #pragma unroll
    for (int i = 0; i < 16; i++)
        #pragma unroll
        for (int j = 0; j < 4; j++) acc[i][j] = 0.f;

    const int NC = K >> 5;

    #pragma unroll
    for (int s = 0; s < STAGES - 1; s++) {
        cp_async16(aSm + s * 8192,        Ag + s * 32);
        cp_async16(aSm + s * 8192 + 4096, Ag + s * 32 + 16);
        cp_async16(bSm + s * 8192,        Bg + s * 32);
        cp_async16(bSm + s * 8192 + 4096, Bg + s * 32 + 16);
        CP_COMMIT();
    }

    for (int c = 0; c < NC; c++) {
        const int st = c & (STAGES - 1);
        CP_WAIT(STAGES - 2);
        __syncthreads();

        #pragma unroll
        for (int sub = 0; sub < 2; sub++) {
            const unsigned* Asb = &As[st][sub * 1024];
            const unsigned* Bsb = &Bs[st][sub * 1024];
            unsigned afr[4][4], bfr[4][2];
            #pragma unroll
            for (int i = 0; i < 4; i++) {
                int blk = (wm * 4 + i) * 4;
                afr[i][0] = Asb[(blk + 0) * 32 + lane];
                afr[i][1] = Asb[(blk + 1) * 32 + lane];
                afr[i][2] = Asb[(blk + 2) * 32 + (lane ^ 16)];
                afr[i][3] = Asb[(blk + 3) * 32 + (lane ^ 16)];
            }
            #pragma unroll
            for (int j = 0; j < 4; j++) {
                int n    = wn * 32 + j * 8 + (lane >> 2);
                int flip = ((n >> 2) & 1) << 2;
                bfr[j][0] = Bsb[n * 8 + ((lane & 3) ^ flip)];
                bfr[j][1] = Bsb[n * 8 + (((lane & 3) + 4) ^ flip)];
            }
            #pragma unroll
            for (int i = 0; i < 4; i++)
                #pragma unroll
                for (int j = 0; j < 4; j++)
                    mma_bf16(acc[i * 4 + j], afr[i], bfr[j]);
        }

        const int nc = c + STAGES - 1;
        if (nc < NC) {
            const int ns = nc & (STAGES - 1);
            cp_async16(aSm + ns * 8192,        Ag + (size_t)nc * 32);
            cp_async16(aSm + ns * 8192 + 4096, Ag + (size_t)nc * 32 + 16);
            cp_async16(bSm + ns * 8192,        Bg + (size_t)nc * 32);
            cp_async16(bSm + ns * 8192 + 4096, Bg + (size_t)nc * 32 + 16);
        }
        CP_COMMIT();
    }

    // ---- epilogue ----
    const int g = lane >> 2, t = lane & 3;
    #pragma unroll
    for (int i = 0; i < 4; i++) {
        int r0 = bm + wm * 64 + i * 16 + g;
        int r1 = r0 + 8;
        int d0 = (MODE == 2) ? dest_row(r0) : r0;
        int d1 = (MODE == 2) ? dest_row(r1) : r1;
        #pragma unroll
        for (int j = 0; j < 4; j++) {
            int col = bn + wn * 32 + j * 8 + t * 2;
            float bc0 = bias[col], bc1 = bias[col + 1];
            float v00 = acc[i * 4 + j][0] + bc0;
            float v01 = acc[i * 4 + j][1] + bc1;
            float v10 = acc[i * 4 + j][2] + bc0;
            float v11 = acc[i * 4 + j][3] + bc1;
            if (MODE == 0 || MODE == 1) {
                if (MODE == 1) {
                    v00 = 0.5f * v00 * (1.0f + erff(v00 * 0.70710678118654752f));
                    v01 = 0.5f * v01 * (1.0f + erff(v01 * 0.70710678118654752f));
                    v10 = 0.5f * v10 * (1.0f + erff(v10 * 0.70710678118654752f));
                    v11 = 0.5f * v11 * (1.0f + erff(v11 * 0.70710678118654752f));
                }
                __nv_bfloat162 p0 = __floats2bfloat162_rn(v00, v01);
                __nv_bfloat162 p1 = __floats2bfloat162_rn(v10, v11);
                *(unsigned*)&Cb[(size_t)r0 * N + col] = *(unsigned*)&p0;
                *(unsigned*)&Cb[(size_t)r1 * N + col] = *(unsigned*)&p1;
            } else {
                v00 += res[(size_t)d0 * N + col];
                v01 += res[(size_t)d0 * N + col + 1];
                v10 += res[(size_t)d1 * N + col];
                v11 += res[(size_t)d1 * N + col + 1];
                *(float2*)&Cf[(size_t)d0 * N + col] = make_float2(v00, v01);
                *(float2*)&Cf[(size_t)d1 * N + col] = make_float2(v10, v11);
            }
        }
    }
}

// ---------------------------------------------------------------------------
// Attention: one CTA per (window, head); bf16 qkv in, bf16 out.
// QK = tensor-core mma (m16n8k16 bf16): q staged as 64x32 A tile, k as
// 56x32 B tile using the SAME verified fragment-slot layouts as gemm_tc
// (raw 16B bf16 copies; ATT_SCALE folded into the S-store epilogue).
// 28 tiles (4x7 of 16x8) across 8 warps; out-of-range rows clamped+discarded.
// Softmax / PV identical to the round-14 passing kernel.
// ---------------------------------------------------------------------------
__device__ __forceinline__ void unpack8(uint4 h, float* dst, float scale)
{
    const __nv_bfloat162* p = (const __nv_bfloat162*)&h;
    #pragma unroll
    for (int e = 0; e < 4; e++) {
        dst[e * 2]     = __low2float(p[e])  * scale;
        dst[e * 2 + 1] = __high2float(p[e]) * scale;
    }
}

__global__ void __launch_bounds__(256)
attn_kernel(const __nv_bfloat16* __restrict__ qkv, const float* __restrict__ relt,
            __nv_bfloat16* __restrict__ outp)
{
    int blk  = blockIdx.x;
    int win  = blk / NHEAD;
    int head = blk % NHEAD;

    __shared__ __align__(16) unsigned Aq[1024];   // q tile 64x32 (2 subs x 512)
    __shared__ __align__(16) unsigned Bk[1024];   // k tile 56x32 (2 subs x 512)
    __shared__ float vv[49][36];
    __shared__ float S [49][56];
    __shared__ float rel_s[169];
    __shared__ int   cnt[49];

    int tid = threadIdx.x;

    // ---- producers: q->A tile, k->B tile (raw bf16 16B copies) ----
    if (tid < 128) {
        int ma = tid >> 1, ha = tid & 1;
        int row = min(ma, 48);
        const uint4* gp = (const uint4*)(qkv + (size_t)(win * 49 + row) * 1152
                                         + head * 32);
        uint4 s0 = gp[ha];        // k 0..15 half (sub 0)
        uint4 s1 = gp[2 + ha];    // k 16..31 half (sub 1)
        int aOff = ((ma >> 4) * 4 + ((ma >> 3) & 1) + 2 * ha) * 32
                 + (((ma & 7) * 4) ^ (ha << 4));
        *(uint4*)&Aq[aOff]       = s0;
        *(uint4*)&Aq[aOff + 512] = s1;
    } else if (tid < 240) {
        int idx = tid - 128;
        int nb = idx >> 1, hb = idx & 1;
        int row = min(nb, 48);
        const uint4* gp = (const uint4*)(qkv + (size_t)(win * 49 + row) * 1152
                                         + head * 32 + 384);
        uint4 s0 = gp[hb];
        uint4 s1 = gp[2 + hb];
        int bOff = nb * 8 + ((hb * 4) ^ (((nb >> 2) & 1) << 2));
        *(uint4*)&Bk[bOff]       = s0;
        *(uint4*)&Bk[bOff + 512] = s1;
    }
    // ---- v (fp32 smem), rel-pos column, region ids ----
    if (tid < 196) {
        int n = tid >> 2, dc = tid & 3;
        uint4 hv = *(const uint4*)&qkv[(size_t)(win * 49 + n) * 1152
                                       + head * 32 + 768 + dc * 8];
        unpack8(hv, &vv[n][dc * 8], 1.0f);
    }
    if (tid < 169) rel_s[tid] = relt[tid * NHEAD + head];
    if (tid < 49) {
        int wi = win & 63;
        int wh = wi >> 3, ww = wi & 7;
        int i = tid / 7, j = tid % 7;
        int h = wh * 7 + i, w = ww * 7 + j;
        int rh = (h < HH - WSZ)   ? 0 : (h < HH - SHIFT   ? 1 : 2);
        int rw = (w < WWID - WSZ) ? 0 : (w < WWID - SHIFT ? 1 : 2);
        cnt[tid] = rh * 3 + rw;
    }
    __syncthreads();

    // ---- QK^T on tensor cores; bias+mask+scale in store ----
    {
        const int warp = tid >> 5, lane = tid & 31;
        const int g = lane >> 2, t4 = lane & 3;
        for (int t = warp; t < 28; t += 8) {
            int tm = t & 3, tn = t >> 2;
            float acc[4] = {0.f, 0.f, 0.f, 0.f};
            #pragma unroll
            for (int sub = 0; sub < 2; sub++) {
                const unsigned* Asb = Aq + sub * 512;
                const unsigned* Bsb = Bk + sub * 512;
                unsigned afr[4], bfr[2];
                int blkA = tm * 4;
                afr[0] = Asb[(blkA + 0) * 32 + lane];
                afr[1] = Asb[(blkA + 1) * 32 + lane];
                afr[2] = Asb[(blkA + 2) * 32 + (lane ^ 16)];
                afr[3] = Asb[(blkA + 3) * 32 + (lane ^ 16)];
                int n    = tn * 8 + g;
                int flip = ((n >> 2) & 1) << 2;
                bfr[0] = Bsb[n * 8 + (t4 ^ flip)];
                bfr[1] = Bsb[n * 8 + ((t4 + 4) ^ flip)];
                mma_bf16(acc, afr, bfr);
            }
            int r0 = tm * 16 + g, r1 = r0 + 8;
            int c0 = tn * 8 + t4 * 2, c1 = c0 + 1;
            if (r0 < 49) {
                int rd = r0 / 7, rm = r0 % 7, cr = cnt[r0];
                if (c0 < 49)
                    S[r0][c0] = acc[0] * ATT_SCALE
                              + rel_s[(rd - c0 / 7 + 6) * 13 + (rm - c0 % 7 + 6)]
                              + ((cr != cnt[c0]) ? -100.f : 0.f);
                if (c1 < 49)
                    S[r0][c1] = acc[1] * ATT_SCALE
                              + rel_s[(rd - c1 / 7 + 6) * 13 + (rm - c1 % 7 + 6)]
                              + ((cr != cnt[c1]) ? -100.f : 0.f);
            }
            if (r1 < 49) {
                int rd = r1 / 7, rm = r1 % 7, cr = cnt[r1];
                if (c0 < 49)
                    S[r1][c0] = acc[2] * ATT_SCALE
                              + rel_s[(rd - c0 / 7 + 6) * 13 + (rm - c0 % 7 + 6)]
                              + ((cr != cnt[c0]) ? -100.f : 0.f);
                if (c1 < 49)
                    S[r1][c1] = acc[3] * ATT_SCALE
                              + rel_s[(rd - c1 / 7 + 6) * 13 + (rm - c1 % 7 + 6)]
                              + ((cr != cnt[c1]) ? -100.f : 0.f);
            }
        }
    }
    __syncthreads();

    // ---- softmax (warp per row) ----
    int wid = tid >> 5, lane = tid & 31;
    for (int n = wid; n < 49; n += 8) {
        float v0 = S[n][lane];
        float v1 = (lane < 17) ? S[n][lane + 32] : -1e30f;
        float mx = fmaxf(v0, v1);
        #pragma unroll
        for (int off = 16; off; off >>= 1)
            mx = fmaxf(mx, __shfl_xor_sync(~0u, mx, off));
        float e0 = expf(v0 - mx);
        float e1 = (lane < 17) ? expf(v1 - mx) : 0.f;
        float sm = e0 + e1;
        #pragma unroll
        for (int off = 16; off; off >>= 1)
            sm += __shfl_xor_sync(~0u, sm, off);
        float inv = 1.f / sm;
        S[n][lane] = e0 * inv;
        if (lane < 17) S[n][lane + 32] = e1 * inv;
    }
    __syncthreads();

    // ---- P @ V, bf16 out ----
    for (int idx = tid; idx < 49 * 8; idx += 256) {
        int n = idx >> 3, dq = idx & 7;
        float a0 = 0.f, a1 = 0.f, a2 = 0.f, a3 = 0.f;
        #pragma unroll 7
        for (int mm = 0; mm < 49; mm++) {
            float s = S[n][mm];
            float4 v = *(const float4*)&vv[mm][dq * 4];
            a0 = fmaf(s, v.x, a0);
            a1 = fmaf(s, v.y, a1);
            a2 = fmaf(s, v.z, a2);
            a3 = fmaf(s, v.w, a3);
        }
        __nv_bfloat162 p0 = __floats2bfloat162_rn(a0, a1);
        __nv_bfloat162 p1 = __floats2bfloat162_rn(a2, a3);
        size_t o = (size_t)(win * 49 + n) * 384 + head * 32 + dq * 4;
        *(uint2*)&outp[o] = make_uint2(*(unsigned*)&p0, *(unsigned*)&p1);
    }
}

// ---------------------------------------------------------------------------
// Launch
// ---------------------------------------------------------------------------
extern "C" void kernel_launch(void* const* d_in, const int* in_sizes, int n_in,
                              void* d_out, int out_size)
{
    const float* x      = (const float*)d_in[0];
    const float* ln1_g  = (const float*)d_in[1];
    const float* ln1_b  = (const float*)d_in[2];
    const float* ln2_g  = (const float*)d_in[3];
    const float* ln2_b  = (const float*)d_in[4];
    const float* qkv_w  = (const float*)d_in[5];
    const float* qkv_b  = (const float*)d_in[6];
    const float* proj_w = (const float*)d_in[7];
    const float* proj_b = (const float*)d_in[8];
    const float* mlp_w1 = (const float*)d_in[9];
    const float* mlp_b1 = (const float*)d_in[10];
    const float* mlp_w2 = (const float*)d_in[11];
    const float* mlp_b2 = (const float*)d_in[12];
    const float* relt   = (const float*)d_in[13];
    float* out = (float*)d_out;

    __nv_bfloat16 *wins, *qkvb, *att, *ln2o, *hbuf, *wtq, *wtp, *wt1, *wt2;
    float *x1;
    cudaGetSymbolAddress((void**)&wins, g_wins);
    cudaGetSymbolAddress((void**)&qkvb, g_qkv);
    cudaGetSymbolAddress((void**)&att,  g_att);
    cudaGetSymbolAddress((void**)&x1,   g_x1);
    cudaGetSymbolAddress((void**)&ln2o, g_ln2);
    cudaGetSymbolAddress((void**)&hbuf, g_h);
    cudaGetSymbolAddress((void**)&wtq,  g_wt_qkv);
    cudaGetSymbolAddress((void**)&wtp,  g_wt_proj);
    cudaGetSymbolAddress((void**)&wt1,  g_wt_m1);
    cudaGetSymbolAddress((void**)&wt2,  g_wt_m2);

    // 0. all weight transposes in one launch
    transpose_all<<<dim3(48, 48, 4), 256>>>(qkv_w, wtq, proj_w, wtp,
                                            mlp_w1, wt1, mlp_w2, wt2);

    // 1. LN1 + cyclic shift + window partition -> bf16
    ln_kernel<<<TOK / 8, 256>>>(x, ln1_g, ln1_b, wins, 1);

    // 2. QKV GEMM: [50176,384] @ [384,1152] -> bf16
    gemm_tc<0><<<dim3(9, TOK / 128), 256>>>(
        wins, wtq, qkv_b, nullptr, nullptr, qkvb, TOK, 1152, 384);

    // 3. Windowed attention -> bf16
    attn_kernel<<<NWIN * NHEAD, 256>>>(qkvb, relt, att);

    // 4. Proj GEMM + window reverse + reverse roll + residual -> fp32
    gemm_tc<2><<<dim3(3, TOK / 128), 256>>>(
        att, wtp, proj_b, x, x1, nullptr, TOK, 384, 384);

    // 5. LN2 -> bf16
    ln_kernel<<<TOK / 8, 256>>>(x1, ln2_g, ln2_b, ln2o, 0);

    // 6. MLP1 + GELU: [50176,384] @ [384,1536] -> bf16
    gemm_tc<1><<<dim3(12, TOK / 128), 256>>>(
        ln2o, wt1, mlp_b1, nullptr, nullptr, hbuf, TOK, 1536, 384);

    // 7. MLP2 + residual: [50176,1536] @ [1536,384] -> d_out
    gemm_tc<3><<<dim3(3, TOK / 128), 256>>>(
        hbuf, wt2, mlp_b2, x1, out, nullptr, TOK, 384, 1536);
}

// round 17
// speedup vs baseline: 1.0810x; 1.0016x over previous
#include <cuda_runtime.h>
#include <cuda_bf16.h>
#include <math.h>
#include <stdint.h>

// ---------------------------------------------------------------------------
// Problem constants
// ---------------------------------------------------------------------------
constexpr int BATCH = 16;
constexpr int HH    = 56;
constexpr int WWID  = 56;
constexpr int CDIM  = 384;
constexpr int NHEAD = 12;
constexpr int WSZ   = 7;
constexpr int SHIFT = 3;
constexpr int NTOK  = 49;
constexpr int NWIN  = BATCH * 64;
constexpr int TOK   = NWIN * NTOK;        // 50176
constexpr float ATT_SCALE = 0.17677669529663687f;
constexpr float LN_EPS    = 1e-3f;

// ---------------------------------------------------------------------------
// Scratch (device globals)
// ---------------------------------------------------------------------------
__device__ __nv_bfloat16 g_wins[TOK * CDIM];
__device__ __nv_bfloat16 g_qkv [TOK * 3 * CDIM];
__device__ __nv_bfloat16 g_att [TOK * CDIM];
__device__ float         g_x1  [TOK * CDIM];
__device__ __nv_bfloat16 g_ln2 [TOK * CDIM];
__device__ __nv_bfloat16 g_h   [TOK * 4 * CDIM];
// transposed bf16 weights [N, K]
__device__ __nv_bfloat16 g_wt_qkv [3 * CDIM * CDIM];
__device__ __nv_bfloat16 g_wt_proj[CDIM * CDIM];
__device__ __nv_bfloat16 g_wt_m1  [4 * CDIM * CDIM];
__device__ __nv_bfloat16 g_wt_m2  [4 * CDIM * CDIM];

// ---------------------------------------------------------------------------
// cp.async helpers
// ---------------------------------------------------------------------------
__device__ __forceinline__ void cp_async16(uint32_t smem, const void* g)
{
    asm volatile("cp.async.cg.shared.global [%0], [%1], 16;"
                 :: "r"(smem), "l"(g));
}
#define CP_COMMIT() asm volatile("cp.async.commit_group;")
#define CP_WAIT(n)  asm volatile("cp.async.wait_group %0;" :: "n"(n))

// ---------------------------------------------------------------------------
// Batched weight transpose + bf16 convert: 4 weights in ONE launch.
// ---------------------------------------------------------------------------
__global__ void __launch_bounds__(256)
transpose_all(const float* __restrict__ W0, __nv_bfloat16* __restrict__ T0,
              const float* __restrict__ W1, __nv_bfloat16* __restrict__ T1,
              const float* __restrict__ W2, __nv_bfloat16* __restrict__ T2,
              const float* __restrict__ W3, __nv_bfloat16* __restrict__ T3)
{
    const float* W; __nv_bfloat16* T; int K, N;
    switch (blockIdx.z) {
        case 0: W = W0; T = T0; K = 384;  N = 1152; break;
        case 1: W = W1; T = T1; K = 384;  N = 384;  break;
        case 2: W = W2; T = T2; K = 384;  N = 1536; break;
        default:W = W3; T = T3; K = 1536; N = 384;  break;
    }
    int kb = blockIdx.x * 32, nb = blockIdx.y * 32;
    if (kb >= K || nb >= N) return;

    __shared__ float t[32][33];
    int x = threadIdx.x & 31, y = threadIdx.x >> 5;   // 32 x 8
    #pragma unroll
    for (int dy = 0; dy < 32; dy += 8)
        t[y + dy][x] = W[(size_t)(kb + y + dy) * N + nb + x];
    __syncthreads();
    #pragma unroll
    for (int dy = 0; dy < 32; dy += 8)
        T[(size_t)(nb + y + dy) * K + kb + x] = __float2bfloat16(t[x][y + dy]);
}

// ---------------------------------------------------------------------------
// LayerNorm: one WARP per token, 8 tokens per 256-thread block.
// gather=1 fuses roll(-3,+3) + window partition. bf16 output.
// ---------------------------------------------------------------------------
__global__ void __launch_bounds__(256)
ln_kernel(const float* __restrict__ X, const float* __restrict__ gam,
          const float* __restrict__ bet, __nv_bfloat16* __restrict__ Y, int gather)
{
    const int warp = threadIdx.x >> 5, lane = threadIdx.x & 31;
    const int tok = blockIdx.x * 8 + warp;
    int src = tok;
    if (gather) {
        int win = tok / NTOK, n = tok % NTOK;
        int b  = win >> 6, wi = win & 63;
        int wh = wi >> 3,  ww = wi & 7;
        int i  = n / WSZ,  j  = n % WSZ;
        int hs = wh * WSZ + i, ws = ww * WSZ + j;
        int sh = hs + SHIFT; if (sh >= HH)  sh -= HH;
        int sw = ws - SHIFT; if (sw < 0)    sw += WWID;
        src = (b * HH + sh) * WWID + sw;
    }
    const float4* xp = (const float4*)(X + (size_t)src * CDIM);
    float4 v0 = xp[lane], v1 = xp[lane + 32], v2 = xp[lane + 64];

    float s  = v0.x + v0.y + v0.z + v0.w
             + v1.x + v1.y + v1.z + v1.w
             + v2.x + v2.y + v2.z + v2.w;
    float s2 = v0.x * v0.x + v0.y * v0.y + v0.z * v0.z + v0.w * v0.w
             + v1.x * v1.x + v1.y * v1.y + v1.z * v1.z + v1.w * v1.w
             + v2.x * v2.x + v2.y * v2.y + v2.z * v2.z + v2.w * v2.w;
    #pragma unroll
    for (int off = 16; off; off >>= 1) {
        s  += __shfl_xor_sync(~0u, s,  off);
        s2 += __shfl_xor_sync(~0u, s2, off);
    }
    const float mu = s * (1.0f / CDIM);
    const float rs = rsqrtf(s2 * (1.0f / CDIM) - mu * mu + LN_EPS);

    const float4* gp = (const float4*)gam;
    const float4* bp = (const float4*)bet;
    uint2* yp = (uint2*)(Y + (size_t)tok * CDIM);

    #pragma unroll
    for (int q = 0; q < 3; q++) {
        float4 v = (q == 0) ? v0 : (q == 1) ? v1 : v2;
        float4 gg = gp[lane + q * 32];
        float4 bb = bp[lane + q * 32];
        float o0 = (v.x - mu) * rs * gg.x + bb.x;
        float o1 = (v.y - mu) * rs * gg.y + bb.y;
        float o2 = (v.z - mu) * rs * gg.z + bb.z;
        float o3 = (v.w - mu) * rs * gg.w + bb.w;
        __nv_bfloat162 p0 = __floats2bfloat162_rn(o0, o1);
        __nv_bfloat162 p1 = __floats2bfloat162_rn(o2, o3);
        yp[lane + q * 32] = make_uint2(*(unsigned*)&p0, *(unsigned*)&p1);
    }
}

__device__ __forceinline__ int dest_row(int tok)
{
    int win = tok / NTOK, n = tok % NTOK;
    int b  = win >> 6, wi = win & 63;
    int wh = wi >> 3,  ww = wi & 7;
    int i  = n / WSZ,  j  = n % WSZ;
    int hs = wh * WSZ + i, ws = ww * WSZ + j;
    int h = hs + SHIFT; if (h >= HH)   h -= HH;
    int w = ws + SHIFT; if (w >= WWID) w -= WWID;
    return (b * HH + h) * WWID + w;
}

// ---------------------------------------------------------------------------
// bf16 mma.sync GEMM. 128x128 CTA tile, 8 warps (64x32), 4-stage cp.async
// pipeline, BK=32/stage — proven backbone, unchanged.
// ---------------------------------------------------------------------------
__device__ __forceinline__ void mma_bf16(float* c, const unsigned* a, const unsigned* b)
{
    asm volatile(
        "mma.sync.aligned.m16n8k16.row.col.f32.bf16.bf16.f32 "
        "{%0,%1,%2,%3}, {%4,%5,%6,%7}, {%8,%9}, {%0,%1,%2,%3};"
        : "+f"(c[0]), "+f"(c[1]), "+f"(c[2]), "+f"(c[3])
        : "r"(a[0]), "r"(a[1]), "r"(a[2]), "r"(a[3]), "r"(b[0]), "r"(b[1]));
}

template<int MODE>
__global__ void __launch_bounds__(256)
gemm_tc(const __nv_bfloat16* __restrict__ A, const __nv_bfloat16* __restrict__ Bt,
        const float* __restrict__ bias, const float* __restrict__ res,
        float* __restrict__ Cf, __nv_bfloat16* __restrict__ Cb,
        int M, int N, int K)
{
    constexpr int STAGES = 4;
    __shared__ __align__(16) unsigned As[STAGES][2048];
    __shared__ __align__(16) unsigned Bs[STAGES][2048];

    const int tid  = threadIdx.x;
    const int bm   = blockIdx.y * 128, bn = blockIdx.x * 128;
    const int warp = tid >> 5, lane = tid & 31;
    const int wm   = warp & 1, wn = warp >> 1;       // 2 x 4 warp grid

    const int ma = tid >> 1, ha = tid & 1;
    const __nv_bfloat16* Ag = A + (size_t)(bm + ma) * K + ha * 8;
    const int aOff = ((ma >> 4) * 4 + ((ma >> 3) & 1) + 2 * ha) * 32
                   + (((ma & 7) * 4) ^ (ha << 4));

    const int nb = tid >> 1, hb = tid & 1;
    const __nv_bfloat16* Bg = Bt + (size_t)(bn + nb) * K + hb * 8;
    const int bOff = nb * 8 + ((hb * 4) ^ (((nb >> 2) & 1) << 2));

    const uint32_t aSm = (uint32_t)__cvta_generic_to_shared(&As[0][0]) + aOff * 4;
    const uint32_t bSm = (uint32_t)__cvta_generic_to_shared(&Bs[0][0]) + bOff * 4;

    float acc[16][4];
    #pragma unroll
    for (int i = 0; i < 16; i++)
        #pragma unroll
        for (int j = 0; j < 4; j++) acc[i][j] = 0.f;

    const int NC = K >> 5;

    #pragma unroll
    for (int s = 0; s < STAGES - 1; s++) {
        cp_async16(aSm + s * 8192,        Ag + s * 32);
        cp_async16(aSm + s * 8192 + 4096, Ag + s * 32 + 16);
        cp_async16(bSm + s * 8192,        Bg + s * 32);
        cp_async16(bSm + s * 8192 + 4096, Bg + s * 32 + 16);
        CP_COMMIT();
    }

    for (int c = 0; c < NC; c++) {
        const int st = c & (STAGES - 1);
        CP_WAIT(STAGES - 2);
        __syncthreads();

        #pragma unroll
        for (int sub = 0; sub < 2; sub++) {
            const unsigned* Asb = &As[st][sub * 1024];
            const unsigned* Bsb = &Bs[st][sub * 1024];
            unsigned afr[4][4], bfr[4][2];
            #pragma unroll
            for (int i = 0; i < 4; i++) {
                int blk = (wm * 4 + i) * 4;
                afr[i][0] = Asb[(blk + 0) * 32 + lane];
                afr[i][1] = Asb[(blk + 1) * 32 + lane];
                afr[i][2] = Asb[(blk + 2) * 32 + (lane ^ 16)];
                afr[i][3] = Asb[(blk + 3) * 32 + (lane ^ 16)];
            }
            #pragma unroll
            for (int j = 0; j < 4; j++) {
                int n    = wn * 32 + j * 8 + (lane >> 2);
                int flip = ((n >> 2) & 1) << 2;
                bfr[j][0] = Bsb[n * 8 + ((lane & 3) ^ flip)];
                bfr[j][1] = Bsb[n * 8 + (((lane & 3) + 4) ^ flip)];
            }
            #pragma unroll
            for (int i = 0; i < 4; i++)
                #pragma unroll
                for (int j = 0; j < 4; j++)
                    mma_bf16(acc[i * 4 + j], afr[i], bfr[j]);
        }

        const int nc = c + STAGES - 1;
        if (nc < NC) {
            const int ns = nc & (STAGES - 1);
            cp_async16(aSm + ns * 8192,        Ag + (size_t)nc * 32);
            cp_async16(aSm + ns * 8192 + 4096, Ag + (size_t)nc * 32 + 16);
            cp_async16(bSm + ns * 8192,        Bg + (size_t)nc * 32);
            cp_async16(bSm + ns * 8192 + 4096, Bg + (size_t)nc * 32 + 16);
        }
        CP_COMMIT();
    }

    // ---- epilogue ----
    const int g = lane >> 2, t = lane & 3;
    #pragma unroll
    for (int i = 0; i < 4; i++) {
        int r0 = bm + wm * 64 + i * 16 + g;
        int r1 = r0 + 8;
        int d0 = (MODE == 2) ? dest_row(r0) : r0;
        int d1 = (MODE == 2) ? dest_row(r1) : r1;
        #pragma unroll
        for (int j = 0; j < 4; j++) {
            int col = bn + wn * 32 + j * 8 + t * 2;
            float bc0 = bias[col], bc1 = bias[col + 1];
            float v00 = acc[i * 4 + j][0] + bc0;
            float v01 = acc[i * 4 + j][1] + bc1;
            float v10 = acc[i * 4 + j][2] + bc0;
            float v11 = acc[i * 4 + j][3] + bc1;
            if (MODE == 0 || MODE == 1) {
                if (MODE == 1) {
                    v00 = 0.5f * v00 * (1.0f + erff(v00 * 0.70710678118654752f));
                    v01 = 0.5f * v01 * (1.0f + erff(v01 * 0.70710678118654752f));
                    v10 = 0.5f * v10 * (1.0f + erff(v10 * 0.70710678118654752f));
                    v11 = 0.5f * v11 * (1.0f + erff(v11 * 0.70710678118654752f));
                }
                __nv_bfloat162 p0 = __floats2bfloat162_rn(v00, v01);
                __nv_bfloat162 p1 = __floats2bfloat162_rn(v10, v11);
                *(unsigned*)&Cb[(size_t)r0 * N + col] = *(unsigned*)&p0;
                *(unsigned*)&Cb[(size_t)r1 * N + col] = *(unsigned*)&p1;
            } else {
                v00 += res[(size_t)d0 * N + col];
                v01 += res[(size_t)d0 * N + col + 1];
                v10 += res[(size_t)d1 * N + col];
                v11 += res[(size_t)d1 * N + col + 1];
                *(float2*)&Cf[(size_t)d0 * N + col] = make_float2(v00, v01);
                *(float2*)&Cf[(size_t)d1 * N + col] = make_float2(v10, v11);
            }
        }
    }
}

// ---------------------------------------------------------------------------
// Attention: one CTA per (window, head); bf16 qkv in, bf16 out.
// QK AND PV both on tensor cores (m16n8k16 bf16, verified fragment layouts).
// PV: P repacked to bf16 A tile (64x64, zero-padded), V^T repacked to B tile
// (32x64) from raw bf16 SMEM (lossless). SMEM buffers unioned with QK's.
// ---------------------------------------------------------------------------
__global__ void __launch_bounds__(256)
attn_kernel(const __nv_bfloat16* __restrict__ qkv, const float* __restrict__ relt,
            __nv_bfloat16* __restrict__ outp)
{
    int blk  = blockIdx.x;
    int win  = blk / NHEAD;
    int head = blk % NHEAD;

    __shared__ __align__(16) unsigned Aq[2048];   // QK A (first 1024) / PV A
    __shared__ __align__(16) unsigned Bk[1024];   // QK B / PV B
    __shared__ float S [49][56];
    __shared__ __nv_bfloat16 vraw[49 * 32];
    __shared__ float rel_s[169];
    __shared__ int   cnt[49];

    int tid = threadIdx.x;

    // ---- producers: q->A tile, k->B tile (raw bf16 16B copies) ----
    if (tid < 128) {
        int ma = tid >> 1, ha = tid & 1;
        int row = min(ma, 48);
        const uint4* gp = (const uint4*)(qkv + (size_t)(win * 49 + row) * 1152
                                         + head * 32);
        uint4 s0 = gp[ha];
        uint4 s1 = gp[2 + ha];
        int aOff = ((ma >> 4) * 4 + ((ma >> 3) & 1) + 2 * ha) * 32
                 + (((ma & 7) * 4) ^ (ha << 4));
        *(uint4*)&Aq[aOff]       = s0;
        *(uint4*)&Aq[aOff + 512] = s1;
    } else if (tid < 240) {
        int idx = tid - 128;
        int nb = idx >> 1, hb = idx & 1;
        int row = min(nb, 48);
        const uint4* gp = (const uint4*)(qkv + (size_t)(win * 49 + row) * 1152
                                         + head * 32 + 384);
        uint4 s0 = gp[hb];
        uint4 s1 = gp[2 + hb];
        int bOff = nb * 8 + ((hb * 4) ^ (((nb >> 2) & 1) << 2));
        *(uint4*)&Bk[bOff]       = s0;
        *(uint4*)&Bk[bOff + 512] = s1;
    }
    // ---- v raw bf16, rel-pos column, region ids ----
    if (tid < 196) {
        int n = tid >> 2, dc = tid & 3;
        uint4 hv = *(const uint4*)&qkv[(size_t)(win * 49 + n) * 1152
                                       + head * 32 + 768 + dc * 8];
        *(uint4*)&vraw[n * 32 + dc * 8] = hv;
    }
    if (tid < 169) rel_s[tid] = relt[tid * NHEAD + head];
    if (tid < 49) {
        int wi = win & 63;
        int wh = wi >> 3, ww = wi & 7;
        int i = tid / 7, j = tid % 7;
        int h = wh * 7 + i, w = ww * 7 + j;
        int rh = (h < HH - WSZ)   ? 0 : (h < HH - SHIFT   ? 1 : 2);
        int rw = (w < WWID - WSZ) ? 0 : (w < WWID - SHIFT ? 1 : 2);
        cnt[tid] = rh * 3 + rw;
    }
    __syncthreads();

    // ---- QK^T on tensor cores; bias+mask+scale in store ----
    {
        const int warp = tid >> 5, lane = tid & 31;
        const int g = lane >> 2, t4 = lane & 3;
        for (int t = warp; t < 28; t += 8) {
            int tm = t & 3, tn = t >> 2;
            float acc[4] = {0.f, 0.f, 0.f, 0.f};
            #pragma unroll
            for (int sub = 0; sub < 2; sub++) {
                const unsigned* Asb = Aq + sub * 512;
                const unsigned* Bsb = Bk + sub * 512;
                unsigned afr[4], bfr[2];
                int blkA = tm * 4;
                afr[0] = Asb[(blkA + 0) * 32 + lane];
                afr[1] = Asb[(blkA + 1) * 32 + lane];
                afr[2] = Asb[(blkA + 2) * 32 + (lane ^ 16)];
                afr[3] = Asb[(blkA + 3) * 32 + (lane ^ 16)];
                int n    = tn * 8 + g;
                int flip = ((n >> 2) & 1) << 2;
                bfr[0] = Bsb[n * 8 + (t4 ^ flip)];
                bfr[1] = Bsb[n * 8 + ((t4 + 4) ^ flip)];
                mma_bf16(acc, afr, bfr);
            }
            int r0 = tm * 16 + g, r1 = r0 + 8;
            int c0 = tn * 8 + t4 * 2, c1 = c0 + 1;
            if (r0 < 49) {
                int rd = r0 / 7, rm = r0 % 7, cr = cnt[r0];
                if (c0 < 49)
                    S[r0][c0] = acc[0] * ATT_SCALE
                              + rel_s[(rd - c0 / 7 + 6) * 13 + (rm - c0 % 7 + 6)]
                              + ((cr != cnt[c0]) ? -100.f : 0.f);
                if (c1 < 49)
                    S[r0][c1] = acc[1] * ATT_SCALE
                              + rel_s[(rd - c1 / 7 + 6) * 13 + (rm - c1 % 7 + 6)]
                              + ((cr != cnt[c1]) ? -100.f : 0.f);
            }
            if (r1 < 49) {
                int rd = r1 / 7, rm = r1 % 7, cr = cnt[r1];
                if (c0 < 49)
                    S[r1][c0] = acc[2] * ATT_SCALE
                              + rel_s[(rd - c0 / 7 + 6) * 13 + (rm - c0 % 7 + 6)]
                              + ((cr != cnt[c0]) ? -100.f : 0.f);
                if (c1 < 49)
                    S[r1][c1] = acc[3] * ATT_SCALE
                              + rel_s[(rd - c1 / 7 + 6) * 13 + (rm - c1 % 7 + 6)]
                              + ((cr != cnt[c1]) ? -100.f : 0.f);
            }
        }
    }
    __syncthreads();

    // ---- softmax (warp per row) ----
    int wid = tid >> 5, lane = tid & 31;
    for (int n = wid; n < 49; n += 8) {
        float v0 = S[n][lane];
        float v1 = (lane < 17) ? S[n][lane + 32] : -1e30f;
        float mx = fmaxf(v0, v1);
        #pragma unroll
        for (int off = 16; off; off >>= 1)
            mx = fmaxf(mx, __shfl_xor_sync(~0u, mx, off));
        float e0 = expf(v0 - mx);
        float e1 = (lane < 17) ? expf(v1 - mx) : 0.f;
        float sm = e0 + e1;
        #pragma unroll
        for (int off = 16; off; off >>= 1)
            sm += __shfl_xor_sync(~0u, sm, off);
        float inv = 1.f / sm;
        S[n][lane] = e0 * inv;
        if (lane < 17) S[n][lane + 32] = e1 * inv;
    }
    __syncthreads();

    // ---- repack P -> bf16 A tile (64x64, zero-padded) ----
    for (int it = tid; it < 2048; it += 256) {
        int kp = it & 31, n = it >> 5;         // n 0..63, kp 0..31
        int sub = kp >> 3, kp7 = kp & 7;
        int m0 = kp * 2, m1 = m0 + 1;
        float lo = 0.f, hi = 0.f;
        if (n < 49) {
            if (m0 < 49) lo = S[n][m0];
            if (m1 < 49) hi = S[n][m1];
        }
        __nv_bfloat162 p = __floats2bfloat162_rn(lo, hi);
        int off = sub * 512
                + ((n >> 4) * 4 + ((n >> 3) & 1) + 2 * (kp7 >> 2)) * 32
                + (((n & 7) * 4 + (kp7 & 3)) ^ ((kp7 >> 2) << 4));
        Aq[off] = *(unsigned*)&p;
    }
    // ---- repack V^T -> bf16 B tile (32x64) : lossless bf16 moves ----
    for (int it = tid; it < 1024; it += 256) {
        int kp = it & 31, d = it >> 5;         // d 0..31
        int sub = kp >> 3, kp7 = kp & 7;
        int m0 = kp * 2, m1 = m0 + 1;
        __nv_bfloat16 lo = (m0 < 49) ? vraw[m0 * 32 + d] : __nv_bfloat16(0.f);
        __nv_bfloat16 hi = (m1 < 49) ? vraw[m1 * 32 + d] : __nv_bfloat16(0.f);
        __nv_bfloat162 p = __halves2bfloat162(lo, hi);
        int off = sub * 256 + d * 8 + (kp7 ^ (((d >> 2) & 1) << 2));
        Bk[off] = *(unsigned*)&p;
    }
    __syncthreads();

    // ---- P @ V on tensor cores; bf16 out ----
    {
        const int warp = tid >> 5;
        const int g = lane >> 2, t4 = lane & 3;
        #pragma unroll
        for (int tt = 0; tt < 2; tt++) {
            int t = warp + tt * 8;
            int tm = t & 3, tn = t >> 2;
            float acc[4] = {0.f, 0.f, 0.f, 0.f};
            #pragma unroll
            for (int sub = 0; sub < 4; sub++) {
                const unsigned* Asb = Aq + sub * 512;
                const unsigned* Bsb = Bk + sub * 256;
                unsigned afr[4], bfr[2];
                int blkA = tm * 4;
                afr[0] = Asb[(blkA + 0) * 32 + lane];
                afr[1] = Asb[(blkA + 1) * 32 + lane];
                afr[2] = Asb[(blkA + 2) * 32 + (lane ^ 16)];
                afr[3] = Asb[(blkA + 3) * 32 + (lane ^ 16)];
                int nn   = tn * 8 + g;
                int flip = ((nn >> 2) & 1) << 2;
                bfr[0] = Bsb[nn * 8 + (t4 ^ flip)];
                bfr[1] = Bsb[nn * 8 + ((t4 + 4) ^ flip)];
                mma_bf16(acc, afr, bfr);
            }
            int r0 = tm * 16 + g, r1 = r0 + 8;
            int c0 = tn * 8 + t4 * 2;
            if (r0 < 49) {
                __nv_bfloat162 p = __floats2bfloat162_rn(acc[0], acc[1]);
                *(unsigned*)&outp[(size_t)(win * 49 + r0) * 384 + head * 32 + c0]
                    = *(unsigned*)&p;
            }
            if (r1 < 49) {
                __nv_bfloat162 p = __floats2bfloat162_rn(acc[2], acc[3]);
                *(unsigned*)&outp[(size_t)(win * 49 + r1) * 384 + head * 32 + c0]
                    = *(unsigned*)&p;
            }
        }
    }
}

// ---------------------------------------------------------------------------
// Launch
// ---------------------------------------------------------------------------
extern "C" void kernel_launch(void* const* d_in, const int* in_sizes, int n_in,
                              void* d_out, int out_size)
{
    const float* x      = (const float*)d_in[0];
    const float* ln1_g  = (const float*)d_in[1];
    const float* ln1_b  = (const float*)d_in[2];
    const float* ln2_g  = (const float*)d_in[3];
    const float* ln2_b  = (const float*)d_in[4];
    const float* qkv_w  = (const float*)d_in[5];
    const float* qkv_b  = (const float*)d_in[6];
    const float* proj_w = (const float*)d_in[7];
    const float* proj_b = (const float*)d_in[8];
    const float* mlp_w1 = (const float*)d_in[9];
    const float* mlp_b1 = (const float*)d_in[10];
    const float* mlp_w2 = (const float*)d_in[11];
    const float* mlp_b2 = (const float*)d_in[12];
    const float* relt   = (const float*)d_in[13];
    float* out = (float*)d_out;

    __nv_bfloat16 *wins, *qkvb, *att, *ln2o, *hbuf, *wtq, *wtp, *wt1, *wt2;
    float *x1;
    cudaGetSymbolAddress((void**)&wins, g_wins);
    cudaGetSymbolAddress((void**)&qkvb, g_qkv);
    cudaGetSymbolAddress((void**)&att,  g_att);
    cudaGetSymbolAddress((void**)&x1,   g_x1);
    cudaGetSymbolAddress((void**)&ln2o, g_ln2);
    cudaGetSymbolAddress((void**)&hbuf, g_h);
    cudaGetSymbolAddress((void**)&wtq,  g_wt_qkv);
    cudaGetSymbolAddress((void**)&wtp,  g_wt_proj);
    cudaGetSymbolAddress((void**)&wt1,  g_wt_m1);
    cudaGetSymbolAddress((void**)&wt2,  g_wt_m2);

    // 0. all weight transposes in one launch
    transpose_all<<<dim3(48, 48, 4), 256>>>(qkv_w, wtq, proj_w, wtp,
                                            mlp_w1, wt1, mlp_w2, wt2);

    // 1. LN1 + cyclic shift + window partition -> bf16
    ln_kernel<<<TOK / 8, 256>>>(x, ln1_g, ln1_b, wins, 1);

    // 2. QKV GEMM: [50176,384] @ [384,1152] -> bf16
    gemm_tc<0><<<dim3(9, TOK / 128), 256>>>(
        wins, wtq, qkv_b, nullptr, nullptr, qkvb, TOK, 1152, 384);

    // 3. Windowed attention -> bf16
    attn_kernel<<<NWIN * NHEAD, 256>>>(qkvb, relt, att);

    // 4. Proj GEMM + window reverse + reverse roll + residual -> fp32
    gemm_tc<2><<<dim3(3, TOK / 128), 256>>>(
        att, wtp, proj_b, x, x1, nullptr, TOK, 384, 384);

    // 5. LN2 -> bf16
    ln_kernel<<<TOK / 8, 256>>>(x1, ln2_g, ln2_b, ln2o, 0);

    // 6. MLP1 + GELU: [50176,384] @ [384,1536] -> bf16
    gemm_tc<1><<<dim3(12, TOK / 128), 256>>>(
        ln2o, wt1, mlp_b1, nullptr, nullptr, hbuf, TOK, 1536, 384);

    // 7. MLP2 + residual: [50176,1536] @ [1536,384] -> d_out
    gemm_tc<3><<<dim3(3, TOK / 128), 256>>>(
        hbuf, wt2, mlp_b2, x1, out, nullptr, TOK, 384, 1536);
}